// round 10
// baseline (speedup 1.0000x reference)
#include <cuda_runtime.h>

// VQ_86139864089353: per-dimension 1D vector quantization — 2 kernels.
// ze: (B, D, 1) f32 ; e: (K, D) f32.  out: [ z (B*D) f32 | zq (B*D) f32 ]
//
// K1 (3 blocks): stable rank via u64 monotone keys (O(K^2)/512 threads),
//                scatter {value, orig} sorted, build guard-banded LUT.
// K2 (768 blks): LUT + short scan -> insertion pos, exact fp32 argmin over
//                4-wide sorted window with reference tie-break (min orig).

#define BN      262144
#define DDIM    3
#define KK      512
#define NBD     (BN * DDIM)
#define NEL     (BN * DDIM)
#define NCELL   2048
#define FLO     (-4.0f)
#define FW      (8.0f / (float)NCELL)    // 1/256 (dyadic)
#define FINVW   ((float)NCELL / 8.0f)    // 256   (dyadic)

#define MBLK    512
#define MVEC    2
#define MGRID   (NEL / (MBLK * MVEC))    // 768

__device__ float2         g_pair[DDIM][KK];    // {sorted value, (float)orig}
__device__ unsigned short g_lut[DDIM][NCELL];

// Monotone (order-preserving) uint32 map of an IEEE754 float.
__device__ __forceinline__ unsigned fkey(float f) {
    unsigned u = __float_as_uint(f);
    return u ^ ((unsigned)((int)u >> 31) | 0x80000000u);
}

// ---------------------------------------------------------------------------
// Kernel 1: rank + scatter + LUT, one block per dim. grid DDIM x KK threads.
// key = mono(value):index  ->  (kj < kk) == (vj<vk || (vj==vk && j<k))
// ---------------------------------------------------------------------------
__global__ void __launch_bounds__(KK)
vq_build(const float* __restrict__ e) {
    const int d = blockIdx.x;
    const int k = threadIdx.x;   // 0..511

    __shared__ unsigned long long s_k[KK];
    __shared__ float              s_sorted[KK];
    __shared__ short              s_org[KK];

    const float v = e[k * DDIM + d];
    const unsigned long long kv =
        ((unsigned long long)fkey(v) << 16) | (unsigned)k;
    s_k[k] = kv;
    __syncthreads();

    int r = 0;
#pragma unroll 8
    for (int j = 0; j < KK; ++j)
        r += (s_k[j] < kv);
    s_sorted[r] = v;
    s_org[r]    = (short)k;
    __syncthreads();

    g_pair[d][k] = make_float2(s_sorted[k], (float)s_org[k]);

    // LUT: conservative lower bound on insertion position (one-cell guard).
    for (int c = k; c < NCELL; c += KK) {
        float edge = FLO + (float)c * FW - FW;
        int lo = 0, hi = KK;
        while (lo < hi) {
            int m = (lo + hi) >> 1;
            if (s_sorted[m] < edge) lo = m + 1; else hi = m;
        }
        g_lut[d][c] = (unsigned short)lo;
    }
}

// ---------------------------------------------------------------------------
// Kernel 2: main. 2 elements/thread, 512-thread blocks.
// ---------------------------------------------------------------------------
__global__ void __launch_bounds__(MBLK, 4)
vq_main(const float2* __restrict__ ze2, float* __restrict__ out) {
    __shared__ float2         s_pair[DDIM][KK];      // 12 KB
    __shared__ unsigned short s_lut[DDIM][NCELL];    // 12 KB

    const int tid = threadIdx.x;
    {
        const float4* src = (const float4*)g_pair;
        float4*       dst = (float4*)s_pair;
        for (int i = tid; i < (int)(DDIM * KK * sizeof(float2) / 16); i += MBLK)
            dst[i] = src[i];
    }
    {
        const uint4* src = (const uint4*)g_lut;
        uint4*       dst = (uint4*)s_lut;
        for (int i = tid; i < (int)(DDIM * NCELL * sizeof(short) / 16); i += MBLK)
            dst[i] = src[i];
    }
    __syncthreads();

    const int t  = blockIdx.x * MBLK + tid;      // float2 index
    const int n0 = t * MVEC;
    float2 xv = ze2[t];
    float xs[MVEC] = {xv.x, xv.y};
    float rz[MVEC], rq[MVEC];

    int d = n0 % 3;
#pragma unroll
    for (int j = 0; j < MVEC; ++j) {
        const float x = xs[j];

        float tt = fminf(fmaxf((x - FLO) * FINVW, 0.0f), (float)(NCELL - 1));
        int i = s_lut[d][(int)tt];
        while (i < KK && s_pair[d][i].x <= x) ++i;

        // Clamp once: window [i2-2, i2+1] is always in-range and is a
        // superset of the true candidate pair {i-1, i} (plus same-side
        // neighbors for fp32-distance ties).
        int i2 = i < 2 ? 2 : (i > KK - 2 ? KK - 2 : i);

        // exact fp32 argmin, tie -> min original index (reference semantics)
        float bestD = __int_as_float(0x7f800000);
        float bestO = 1.0e9f;
        float bestV = 0.0f;
#pragma unroll
        for (int off = -2; off <= 1; ++off) {
            float2 p = s_pair[d][i2 + off];
            float dx = x - p.x;
            float dd = dx * dx;                  // same fp32 op as reference
            bool take = (dd < bestD) || (dd == bestD && p.y < bestO);
            bestD = take ? dd : bestD;
            bestO = take ? p.y : bestO;
            bestV = take ? p.x : bestV;
        }
        rz[j] = bestO;
        rq[j] = bestV;

        d = (d == 2) ? 0 : d + 1;
    }

    ((float2*)out)[t]         = make_float2(rz[0], rz[1]);
    ((float2*)(out + NBD))[t] = make_float2(rq[0], rq[1]);
}

// ---------------------------------------------------------------------------
extern "C" void kernel_launch(void* const* d_in, const int* in_sizes, int n_in,
                              void* d_out, int out_size) {
    const float* ze = (const float*)d_in[0];   // (B, D, 1)
    const float* e  = (const float*)d_in[1];   // (K, D)
    float* out = (float*)d_out;

    vq_build<<<DDIM, KK>>>(e);
    vq_main<<<MGRID, MBLK>>>((const float2*)ze, out);
}

// round 11
// speedup vs baseline: 1.1083x; 1.1083x over previous
#include <cuda_runtime.h>

// VQ_86139864089353: per-dimension 1D vector quantization — 2 kernels.
// ze: (B, D, 1) f32 ; e: (K, D) f32.  out: [ z (B*D) f32 | zq (B*D) f32 ]
//
// K1 (48 blocks): partial stable ranks (u64 monotone keys); blocks 0..2
//                 combine, scatter sorted {val,orig}, build fine LUT.
// K2 (768 blocks): LUT start + 5 fixed candidates + rare extension, all
//                  evaluated with exact fp32 dd and u64 lexicographic
//                  key-min (dd, orig, c) == reference argmin semantics.

#define BN      262144
#define DDIM    3
#define KK      512
#define NBD     (BN * DDIM)
#define NEL     (BN * DDIM)
#define NCELL   4096
#define FLO     (-4.0f)
#define FW      0.001953125f             // 1/512 (dyadic)
#define FINVW   512.0f
#define GUARD   0x1p-19f                 // covers cell-map fl rounding (<=2^-20)
#define JPARTS  16
#define JCH     (KK / JPARTS)            // 32
#define RBLKS   (DDIM * JPARTS)          // 48

#define MBLK    512
#define MVEC    2
#define MGRID   (NEL / (MBLK * MVEC))    // 768

__device__ int            g_rankp[DDIM][JPARTS][KK];  // plain stores, idempotent
__device__ uint2          g_tab[DDIM][KK];            // {val bits, orig}
__device__ unsigned short g_lut[DDIM][NCELL];
__device__ int            g_cnt1, g_cnt2;             // 0 at rest (self-reset)

// Monotone (order-preserving) uint32 map of an IEEE754 float.
__device__ __forceinline__ unsigned fkey(float f) {
    unsigned u = __float_as_uint(f);
    return u ^ ((unsigned)((int)u >> 31) | 0x80000000u);
}

// ---------------------------------------------------------------------------
// Kernel 1: ranks (48 blocks) + build (blocks 0..2 poll then finish).
// ---------------------------------------------------------------------------
__global__ void __launch_bounds__(KK)
vq_prep(const float* __restrict__ e) {
    const int b   = blockIdx.x;
    const int tid = threadIdx.x;          // 0..511
    const int d   = b % DDIM;
    const int p   = b / DDIM;             // 0..15

    __shared__ unsigned long long s_k[JCH];
    __shared__ float              s_sorted[KK];
    __shared__ short              s_org[KK];

    // partial stable rank for slice p
    if (tid < JCH) {
        int j = p * JCH + tid;
        s_k[tid] = ((unsigned long long)fkey(e[j * DDIM + d]) << 16) | (unsigned)j;
    }
    __syncthreads();
    {
        const unsigned long long kv =
            ((unsigned long long)fkey(e[tid * DDIM + d]) << 16) | (unsigned)tid;
        int r = 0;
#pragma unroll
        for (int j = 0; j < JCH; ++j) r += (s_k[j] < kv);
        g_rankp[d][p][tid] = r;
    }
    __threadfence();
    __syncthreads();
    if (tid == 0) atomicAdd(&g_cnt1, 1);

    if (b >= DDIM) return;

    // ---- builder blocks 0..2 (d == b) ----
    if (tid == 0) {
        while (*(volatile int*)&g_cnt1 != RBLKS) __nanosleep(128);
    }
    __syncthreads();
    __threadfence();   // acquire

    int r = 0;
#pragma unroll
    for (int q = 0; q < JPARTS; ++q) r += g_rankp[d][q][tid];

    const float v = e[tid * DDIM + d];
    s_sorted[r] = v;
    s_org[r]    = (short)tid;
    __syncthreads();

    g_tab[d][tid] = make_uint2(__float_as_uint(s_sorted[tid]),
                               (unsigned)s_org[tid]);

    // LUT: lower bound on insertion position with tiny guard.
    for (int c = tid; c < NCELL; c += KK) {
        float edge = fmaf((float)c, FW, FLO) - GUARD;
        int lo = 0, hi = KK;
        while (lo < hi) {
            int m = (lo + hi) >> 1;
            if (s_sorted[m] < edge) lo = m + 1; else hi = m;
        }
        g_lut[d][c] = (unsigned short)lo;
    }

    __threadfence();
    __syncthreads();
    if (tid == 0) {
        if (atomicAdd(&g_cnt2, 1) == DDIM - 1) {   // last builder cleans up
            g_cnt1 = 0;
            __threadfence();
            g_cnt2 = 0;
        }
    }
}

// ---------------------------------------------------------------------------
// Kernel 2: main. 2 elements/thread, 512-thread blocks, grid 768.
// ---------------------------------------------------------------------------
__global__ void __launch_bounds__(MBLK, 4)
vq_main(const float2* __restrict__ ze2, float* __restrict__ out) {
    __shared__ uint2          s_tab[DDIM][KK];       // 12 KB
    __shared__ unsigned short s_lut[DDIM][NCELL];    // 24 KB

    const int tid = threadIdx.x;
    {
        const uint4* src = (const uint4*)g_tab;
        uint4*       dst = (uint4*)s_tab;
        for (int i = tid; i < (int)(DDIM * KK * sizeof(uint2) / 16); i += MBLK)
            dst[i] = src[i];
    }
    {
        const uint4* src = (const uint4*)g_lut;
        uint4*       dst = (uint4*)s_lut;
        for (int i = tid; i < (int)(DDIM * NCELL * sizeof(short) / 16); i += MBLK)
            dst[i] = src[i];
    }
    __syncthreads();

    const int t  = blockIdx.x * MBLK + tid;      // float2 index
    const int n0 = t * MVEC;
    float2 xv = ze2[t];
    float xs[MVEC] = {xv.x, xv.y};
    float rz[MVEC], rq[MVEC];

    int d = n0 % 3;
#pragma unroll
    for (int j = 0; j < MVEC; ++j) {
        const float x = xs[j];
        const uint2* tab = &s_tab[d][0];

        float tt = fminf(fmaxf((x - FLO) * FINVW, 0.0f), (float)(NCELL - 1));
        int lo = s_lut[d][(int)tt];
        int a  = lo < 2 ? 2 : (lo > KK - 3 ? KK - 3 : lo);   // [a-2, a+2] in range

        // candidates [a-2, a+2]: key = (dd_bits : orig : c), min == reference
        // argmin with first-original-index tie-break.
        unsigned long long best = ~0ull;
        float w0 = 0.0f, w1 = 0.0f;
#pragma unroll
        for (int u = -2; u <= 2; ++u) {
            int c = a + u;
            uint2 pp = tab[c];
            float v  = __uint_as_float(pp.x);
            float dx = x - v;
            float dd = dx * dx;                  // same fp32 op as reference
            unsigned long long key =
                ((unsigned long long)__float_as_uint(dd) << 32)
              | (unsigned long long)(pp.y << 16) | (unsigned)c;
            best = best < key ? best : key;
            if (u == 1) w0 = v;
            if (u == 2) w1 = v;
        }

        // rare extension: candidate c needed iff c <= ub(x)+1 <=> val(c-2) <= x
        int c = a + 3;
        while (w0 <= x && c < KK) {
            uint2 pp = tab[c];
            float v  = __uint_as_float(pp.x);
            float dx = x - v;
            float dd = dx * dx;
            unsigned long long key =
                ((unsigned long long)__float_as_uint(dd) << 32)
              | (unsigned long long)(pp.y << 16) | (unsigned)c;
            best = best < key ? best : key;
            w0 = w1; w1 = v; ++c;
        }

        int cwin = (int)(best & 0xFFFFu);
        int orig = (int)((best >> 16) & 0xFFFFu);
        rz[j] = (float)orig;
        rq[j] = __uint_as_float(tab[cwin].x);

        d = (d == 2) ? 0 : d + 1;
    }

    ((float2*)out)[t]         = make_float2(rz[0], rz[1]);
    ((float2*)(out + NBD))[t] = make_float2(rq[0], rq[1]);
}

// ---------------------------------------------------------------------------
extern "C" void kernel_launch(void* const* d_in, const int* in_sizes, int n_in,
                              void* d_out, int out_size) {
    const float* ze = (const float*)d_in[0];   // (B, D, 1)
    const float* e  = (const float*)d_in[1];   // (K, D)
    float* out = (float*)d_out;

    vq_prep<<<RBLKS, KK>>>(e);
    vq_main<<<MGRID, MBLK>>>((const float2*)ze, out);
}